// round 15
// baseline (speedup 1.0000x reference)
#include <cuda_runtime.h>

// Problem constants (fixed by setup_inputs: x,y = [8,3,512,512] fp32)
#define HH 512
#define WW 512
#define NC 24              // 8*3 planes
#define TILE_W 32
#define TILE_H 64
#define HALO 5
#define ROWS_H (TILE_H + 2 * HALO)   // 74 hpass rows
#define SW 36                        // padded smem row stride (floats)
#define TPX 16             // col tiles (512/32)
#define TPY 8              // row tiles (512/64)
#define NBLK (NC * TPX * TPY)        // 3072
#define NTHREADS 256
#define PLANE_H (ROWS_H * SW)        // 2664 floats per hpass plane

#define C3 1e-4f
#define EPSV 1e-12f

__device__ float g_partials[NBLK];
__device__ int   g_counter;      // zero-initialized; self-resets each call

// Gaussian(sigma=1.5, K=11), normalized — matches reference to ~1e-7
#define W0 0.00102838f
#define W1 0.00759876f
#define W2 0.03600077f
#define W3 0.10936079f
#define W4 0.21300554f
#define W5 0.26601172f

typedef unsigned long long ull;

__device__ __forceinline__ ull pack2(float lo, float hi) {
    ull r; asm("mov.b64 %0, {%1, %2};" : "=l"(r) : "f"(lo), "f"(hi)); return r;
}
__device__ __forceinline__ void unpack2(ull v, float& lo, float& hi) {
    asm("mov.b64 {%0, %1}, %2;" : "=f"(lo), "=f"(hi) : "l"(v));
}
__device__ __forceinline__ ull fma2(ull a, ull b, ull c) {
    ull d; asm("fma.rn.f32x2 %0, %1, %2, %3;" : "=l"(d) : "l"(a), "l"(b), "l"(c)); return d;
}

template <bool INTERIOR>
__device__ __forceinline__ void load20(const float* __restrict__ p, int gr, int gc0,
                                       float v[20])
{
    #pragma unroll
    for (int q = 0; q < 5; q++) {
        const int gc = gc0 + 4 * q;
        float4 f;
        if (INTERIOR || ((unsigned)gr < HH && (unsigned)gc < WW)) {
            f = *(const float4*)(p + gr * WW + gc);
        } else {
            f = make_float4(0.f, 0.f, 0.f, 0.f);
        }
        v[4*q+0] = f.x; v[4*q+1] = f.y; v[4*q+2] = f.z; v[4*q+3] = f.w;
    }
}

__device__ __forceinline__ void store4(float* dst, const float a[4]) {
    *(float4*)dst = make_float4(a[0], a[1], a[2], a[3]);
}

template <bool INTERIOR>
__device__ __forceinline__ void hpass(const float* __restrict__ xp,
                                      const float* __restrict__ yp,
                                      float* __restrict__ s_h,
                                      int row0, int col0, int tid)
{
    const float wgt[11] = {W0, W1, W2, W3, W4, W5, W4, W3, W2, W1, W0};
    // items: 74 rows x 8 groups of 4 outputs = 592
    for (int i = tid; i < ROWS_H * 8; i += NTHREADS) {
        const int r = i >> 3, g = i & 7;
        const int gr  = row0 + r - HALO;
        const int gc0 = col0 + 4 * g - 8;   // window covers output cols 4g..4g+3
        float* dst = s_h + r * SW + 4 * g;

        float av[20], bv[20];
        load20<INTERIOR>(xp, gr, gc0, av);
        load20<INTERIOR>(yp, gr, gc0, bv);

        // ---- a-phase sweep: mu_x and E[xx] together ----
        {
            float mux[4] = {0.f, 0.f, 0.f, 0.f};
            float xx[4]  = {0.f, 0.f, 0.f, 0.f};
            #pragma unroll
            for (int s = 3; s <= 16; s++) {
                const float a  = av[s];
                const float aa = a * a;
                #pragma unroll
                for (int j = 0; j < 4; j++) {
                    const int k = s - 3 - j;
                    if (k >= 0 && k <= 10) {
                        mux[j] = fmaf(a,  wgt[k], mux[j]);
                        xx[j]  = fmaf(aa, wgt[k], xx[j]);
                    }
                }
            }
            store4(dst + 0 * PLANE_H, mux);
            store4(dst + 3 * PLANE_H, xx);
        }

        // ---- b-phase sweep: mu_y, E[yy], E[xy] together ----
        {
            float muy[4] = {0.f, 0.f, 0.f, 0.f};
            float yy[4]  = {0.f, 0.f, 0.f, 0.f};
            float xy[4]  = {0.f, 0.f, 0.f, 0.f};
            #pragma unroll
            for (int s = 3; s <= 16; s++) {
                const float b  = bv[s];
                const float bb = b * b;
                const float ab = av[s] * b;
                #pragma unroll
                for (int j = 0; j < 4; j++) {
                    const int k = s - 3 - j;
                    if (k >= 0 && k <= 10) {
                        muy[j] = fmaf(b,  wgt[k], muy[j]);
                        yy[j]  = fmaf(bb, wgt[k], yy[j]);
                        xy[j]  = fmaf(ab, wgt[k], xy[j]);
                    }
                }
            }
            store4(dst + 1 * PLANE_H, muy);
            store4(dst + 2 * PLANE_H, xy);
            store4(dst + 4 * PLANE_H, yy);
        }
    }
}

// Streaming vertical 11-tap conv over a column pair: 4 output rows, f32x2 packed.
__device__ __forceinline__ void vconv4(const float* __restrict__ colp,
                                       const ull w2[11], ull acc[4])
{
    acc[0] = acc[1] = acc[2] = acc[3] = 0ull;
    #pragma unroll
    for (int k = 0; k < 14; k++) {
        const ull v = *(const ull*)(colp + k * SW);
        #pragma unroll
        for (int r = 0; r < 4; r++) {
            const int j = k - r;
            if (j >= 0 && j <= 10) acc[r] = fma2(v, w2[j], acc[r]);
        }
    }
}

__global__ __launch_bounds__(NTHREADS, 4) void ssim_structure_kernel(
    const float* __restrict__ x, const float* __restrict__ y, float* __restrict__ out)
{
    __shared__ float s_h[5 * PLANE_H];      // 53280 B
    __shared__ float warpsum[8];
    __shared__ bool  is_last;

    const int tid  = threadIdx.x;
    const int row0 = blockIdx.y * TILE_H;
    const int col0 = blockIdx.x * TILE_W;
    const float* xp = x + (size_t)blockIdx.z * (HH * WW);
    const float* yp = y + (size_t)blockIdx.z * (HH * WW);

    const bool interior = (row0 >= HALO) && (row0 + ROWS_H - HALO <= HH) &&
                          (col0 >= 8)    && (col0 + TILE_W + 4 <= WW);
    if (interior) hpass<true >(xp, yp, s_h, row0, col0, tid);
    else          hpass<false>(xp, yp, s_h, row0, col0, tid);
    __syncthreads();

    // ---- vertical pass: thread = 2 cols x 4 rows; planes streamed, f32x2 ----
    float lsum = 0.0f;
    {
        const int cp = tid & 15;             // column pair (cols 2cp, 2cp+1)
        const int r0 = (tid >> 4) * 4;       // output rows r0..r0+3
        ull w2[11];
        {
            const float wgt[11] = {W0, W1, W2, W3, W4, W5, W4, W3, W2, W1, W0};
            #pragma unroll
            for (int k = 0; k < 11; k++) w2[k] = pack2(wgt[k], wgt[k]);
        }
        const float* base = s_h + r0 * SW + 2 * cp;
        ull acc[4];

        float mx[4][2], my[4][2], sxy[4][2], sx[4][2], sy[4][2];

        vconv4(base + 0 * PLANE_H, w2, acc);                     // mu_x
        #pragma unroll
        for (int r = 0; r < 4; r++) unpack2(acc[r], mx[r][0], mx[r][1]);

        vconv4(base + 1 * PLANE_H, w2, acc);                     // mu_y
        #pragma unroll
        for (int r = 0; r < 4; r++) unpack2(acc[r], my[r][0], my[r][1]);

        vconv4(base + 2 * PLANE_H, w2, acc);                     // E[xy]
        #pragma unroll
        for (int r = 0; r < 4; r++) {
            float e0, e1; unpack2(acc[r], e0, e1);
            sxy[r][0] = e0 - mx[r][0] * my[r][0];
            sxy[r][1] = e1 - mx[r][1] * my[r][1];
        }

        vconv4(base + 3 * PLANE_H, w2, acc);                     // E[xx]
        #pragma unroll
        for (int r = 0; r < 4; r++) {
            float e0, e1; unpack2(acc[r], e0, e1);
            sx[r][0] = fmaxf(e0 - mx[r][0] * mx[r][0], EPSV);
            sx[r][1] = fmaxf(e1 - mx[r][1] * mx[r][1], EPSV);
        }

        vconv4(base + 4 * PLANE_H, w2, acc);                     // E[yy]
        #pragma unroll
        for (int r = 0; r < 4; r++) {
            float e0, e1; unpack2(acc[r], e0, e1);
            sy[r][0] = fmaxf(e0 - my[r][0] * my[r][0], EPSV);
            sy[r][1] = fmaxf(e1 - my[r][1] * my[r][1], EPSV);
        }

        #pragma unroll
        for (int r = 0; r < 4; r++) {
            #pragma unroll
            for (int j = 0; j < 2; j++) {
                lsum += __fdividef(sxy[r][j] + C3,
                                   sqrtf(sx[r][j] * sy[r][j]) + C3);
            }
        }
    }

    // ---- block reduction -> partial ----
    #pragma unroll
    for (int o = 16; o; o >>= 1)
        lsum += __shfl_down_sync(0xffffffffu, lsum, o);
    if ((tid & 31) == 0) warpsum[tid >> 5] = lsum;
    __syncthreads();
    if (tid == 0) {
        float v = 0.0f;
        #pragma unroll
        for (int w = 0; w < 8; w++) v += warpsum[w];
        const int bid = (blockIdx.z * TPY + blockIdx.y) * TPX + blockIdx.x;
        g_partials[bid] = v;
        __threadfence();
        const int done = atomicAdd(&g_counter, 1);
        is_last = (done == NBLK - 1);
    }
    __syncthreads();

    // ---- last block: deterministic final reduction ----
    if (is_last) {
        float s = 0.0f;
        for (int i = tid; i < NBLK; i += NTHREADS) s += g_partials[i];
        #pragma unroll
        for (int o = 16; o; o >>= 1)
            s += __shfl_down_sync(0xffffffffu, s, o);
        if ((tid & 31) == 0) warpsum[tid >> 5] = s;
        __syncthreads();
        if (tid == 0) {
            float v = 0.0f;
            #pragma unroll
            for (int w = 0; w < 8; w++) v += warpsum[w];
            const float denom = 1.0f / ((float)NC * (float)HH * (float)WW);
            out[0] = 1.0f - v * denom;
            g_counter = 0;   // self-reset for the next (graph-replayed) call
        }
    }
}

extern "C" void kernel_launch(void* const* d_in, const int* in_sizes, int n_in,
                              void* d_out, int out_size)
{
    (void)in_sizes; (void)n_in; (void)out_size;
    const float* x = (const float*)d_in[0];
    const float* y = (const float*)d_in[1];
    float* out = (float*)d_out;

    dim3 grid(TPX, TPY, NC);
    ssim_structure_kernel<<<grid, NTHREADS>>>(x, y, out);
}

// round 16
// speedup vs baseline: 1.0574x; 1.0574x over previous
#include <cuda_runtime.h>

// Problem constants (fixed by setup_inputs: x,y = [8,3,512,512] fp32)
#define HH 512
#define WW 512
#define NC 24              // 8*3 planes
#define TILE_W 32
#define TILE_H 64
#define HALO 5
#define ROWS_H (TILE_H + 2 * HALO)   // 74 hpass rows
#define SW 36                        // padded smem row stride (floats)
#define TPX 16             // col tiles (512/32)
#define TPY 8              // row tiles (512/64)
#define NBLK (NC * TPX * TPY)        // 3072
#define NTHREADS 256
#define PLANE_H (ROWS_H * SW)        // 2664 floats per hpass plane

#define C3 1e-4f
#define EPSV 1e-12f

__device__ float g_partials[NBLK];
__device__ int   g_counter;      // zero-initialized; self-resets each call

// Gaussian(sigma=1.5, K=11), normalized — matches reference to ~1e-7
#define W0 0.00102838f
#define W1 0.00759876f
#define W2 0.03600077f
#define W3 0.10936079f
#define W4 0.21300554f
#define W5 0.26601172f

typedef unsigned long long ull;

__device__ __forceinline__ ull pack2(float lo, float hi) {
    ull r; asm("mov.b64 %0, {%1, %2};" : "=l"(r) : "f"(lo), "f"(hi)); return r;
}
__device__ __forceinline__ void unpack2(ull v, float& lo, float& hi) {
    asm("mov.b64 {%0, %1}, %2;" : "=f"(lo), "=f"(hi) : "l"(v));
}
__device__ __forceinline__ ull fma2(ull a, ull b, ull c) {
    ull d; asm("fma.rn.f32x2 %0, %1, %2, %3;" : "=l"(d) : "l"(a), "l"(b), "l"(c)); return d;
}

// 11-tap conv producing 4 outputs from v[base .. base+13] (scalar FFMA-imm)
__device__ __forceinline__ void conv4(const float* v, int base, float acc[4]) {
    const float wgt[11] = {W0, W1, W2, W3, W4, W5, W4, W3, W2, W1, W0};
    acc[0] = acc[1] = acc[2] = acc[3] = 0.0f;
    #pragma unroll
    for (int k = 0; k < 11; k++) {
        const float w = wgt[k];
        #pragma unroll
        for (int j = 0; j < 4; j++)
            acc[j] = fmaf(v[base + j + k], w, acc[j]);
    }
}

template <bool INTERIOR>
__device__ __forceinline__ void hpass(const float* __restrict__ xp,
                                      const float* __restrict__ yp,
                                      float* __restrict__ s_h,
                                      int row0, int col0, int tid)
{
    // items: 74 rows x 8 groups of 4 outputs = 592
    for (int i = tid; i < ROWS_H * 8; i += NTHREADS) {
        const int r = i >> 3, g = i & 7;
        const int gr  = row0 + r - HALO;
        const int gc0 = col0 + 4 * g - 8;   // aligned float4 base (taps -5..+8 of col 4g)

        float av[20], bv[20];
        #pragma unroll
        for (int q = 0; q < 5; q++) {
            const int gc = gc0 + 4 * q;
            float4 fa, fb;
            if (INTERIOR || ((unsigned)gr < HH && (unsigned)gc < WW)) {
                fa = *(const float4*)(xp + gr * WW + gc);
                fb = *(const float4*)(yp + gr * WW + gc);
            } else {
                fa = make_float4(0.f, 0.f, 0.f, 0.f);
                fb = fa;
            }
            av[4*q+0] = fa.x; av[4*q+1] = fa.y; av[4*q+2] = fa.z; av[4*q+3] = fa.w;
            bv[4*q+0] = fb.x; bv[4*q+1] = fb.y; bv[4*q+2] = fb.z; bv[4*q+3] = fb.w;
        }
        float acc[4];
        float* dst = s_h + r * SW + 4 * g;

        conv4(av, 3, acc);                                   // mu_x
        *(float4*)(dst + 0 * PLANE_H) = make_float4(acc[0], acc[1], acc[2], acc[3]);
        conv4(bv, 3, acc);                                   // mu_y
        *(float4*)(dst + 1 * PLANE_H) = make_float4(acc[0], acc[1], acc[2], acc[3]);

        float t[14];
        #pragma unroll
        for (int m = 0; m < 14; m++) t[m] = av[m+3] * bv[m+3];
        conv4(t, 0, acc);                                    // E[xy]
        *(float4*)(dst + 2 * PLANE_H) = make_float4(acc[0], acc[1], acc[2], acc[3]);

        #pragma unroll
        for (int m = 0; m < 14; m++) t[m] = av[m+3] * av[m+3];
        conv4(t, 0, acc);                                    // E[xx]
        *(float4*)(dst + 3 * PLANE_H) = make_float4(acc[0], acc[1], acc[2], acc[3]);

        #pragma unroll
        for (int m = 0; m < 14; m++) t[m] = bv[m+3] * bv[m+3];
        conv4(t, 0, acc);                                    // E[yy]
        *(float4*)(dst + 4 * PLANE_H) = make_float4(acc[0], acc[1], acc[2], acc[3]);
    }
}

// Streaming vertical 11-tap conv over a column pair: 4 output rows, f32x2 packed.
// Loads 14 rows once; registers hold only the accumulators.
__device__ __forceinline__ void vconv4(const float* __restrict__ colp,
                                       const ull w2[11], ull acc[4])
{
    acc[0] = acc[1] = acc[2] = acc[3] = 0ull;
    #pragma unroll
    for (int k = 0; k < 14; k++) {
        const ull v = *(const ull*)(colp + k * SW);
        #pragma unroll
        for (int r = 0; r < 4; r++) {
            const int j = k - r;
            if (j >= 0 && j <= 10) acc[r] = fma2(v, w2[j], acc[r]);
        }
    }
}

__global__ __launch_bounds__(NTHREADS, 4) void ssim_structure_kernel(
    const float* __restrict__ x, const float* __restrict__ y, float* __restrict__ out)
{
    __shared__ float s_h[5 * PLANE_H];      // 53280 B
    __shared__ float warpsum[8];
    __shared__ bool  is_last;

    const int tid  = threadIdx.x;
    const int row0 = blockIdx.y * TILE_H;
    const int col0 = blockIdx.x * TILE_W;
    const float* xp = x + (size_t)blockIdx.z * (HH * WW);
    const float* yp = y + (size_t)blockIdx.z * (HH * WW);

    const bool interior = (row0 >= HALO) && (row0 + ROWS_H - HALO <= HH) &&
                          (col0 >= 8)    && (col0 + TILE_W + 4 <= WW);
    if (interior) hpass<true >(xp, yp, s_h, row0, col0, tid);
    else          hpass<false>(xp, yp, s_h, row0, col0, tid);
    __syncthreads();

    // ---- vertical pass: thread = 2 cols x 4 rows; planes streamed ----
    float lsum = 0.0f;
    {
        const int cp = tid & 15;             // column pair (cols 2cp, 2cp+1)
        const int r0 = (tid >> 4) * 4;       // output rows r0..r0+3
        ull w2[11];
        {
            const float wgt[11] = {W0, W1, W2, W3, W4, W5, W4, W3, W2, W1, W0};
            #pragma unroll
            for (int k = 0; k < 11; k++) w2[k] = pack2(wgt[k], wgt[k]);
        }
        const float* base = s_h + r0 * SW + 2 * cp;
        ull acc[4];

        float mx[4][2], my[4][2], sxy[4][2], sx[4][2], sy[4][2];

        vconv4(base + 0 * PLANE_H, w2, acc);                     // mu_x
        #pragma unroll
        for (int r = 0; r < 4; r++) unpack2(acc[r], mx[r][0], mx[r][1]);

        vconv4(base + 1 * PLANE_H, w2, acc);                     // mu_y
        #pragma unroll
        for (int r = 0; r < 4; r++) unpack2(acc[r], my[r][0], my[r][1]);

        vconv4(base + 2 * PLANE_H, w2, acc);                     // E[xy]
        #pragma unroll
        for (int r = 0; r < 4; r++) {
            float e0, e1; unpack2(acc[r], e0, e1);
            sxy[r][0] = e0 - mx[r][0] * my[r][0];
            sxy[r][1] = e1 - mx[r][1] * my[r][1];
        }

        vconv4(base + 3 * PLANE_H, w2, acc);                     // E[xx]
        #pragma unroll
        for (int r = 0; r < 4; r++) {
            float e0, e1; unpack2(acc[r], e0, e1);
            sx[r][0] = fmaxf(e0 - mx[r][0] * mx[r][0], EPSV);
            sx[r][1] = fmaxf(e1 - mx[r][1] * mx[r][1], EPSV);
        }

        vconv4(base + 4 * PLANE_H, w2, acc);                     // E[yy]
        #pragma unroll
        for (int r = 0; r < 4; r++) {
            float e0, e1; unpack2(acc[r], e0, e1);
            sy[r][0] = fmaxf(e0 - my[r][0] * my[r][0], EPSV);
            sy[r][1] = fmaxf(e1 - my[r][1] * my[r][1], EPSV);
        }

        #pragma unroll
        for (int r = 0; r < 4; r++) {
            #pragma unroll
            for (int j = 0; j < 2; j++) {
                lsum += __fdividef(sxy[r][j] + C3,
                                   sqrtf(sx[r][j] * sy[r][j]) + C3);
            }
        }
    }

    // ---- block reduction -> partial ----
    #pragma unroll
    for (int o = 16; o; o >>= 1)
        lsum += __shfl_down_sync(0xffffffffu, lsum, o);
    if ((tid & 31) == 0) warpsum[tid >> 5] = lsum;
    __syncthreads();
    if (tid == 0) {
        float v = 0.0f;
        #pragma unroll
        for (int w = 0; w < 8; w++) v += warpsum[w];
        const int bid = (blockIdx.z * TPY + blockIdx.y) * TPX + blockIdx.x;
        g_partials[bid] = v;
        __threadfence();
        const int done = atomicAdd(&g_counter, 1);
        is_last = (done == NBLK - 1);
    }
    __syncthreads();

    // ---- last block: deterministic final reduction ----
    if (is_last) {
        float s = 0.0f;
        for (int i = tid; i < NBLK; i += NTHREADS) s += g_partials[i];
        #pragma unroll
        for (int o = 16; o; o >>= 1)
            s += __shfl_down_sync(0xffffffffu, s, o);
        if ((tid & 31) == 0) warpsum[tid >> 5] = s;
        __syncthreads();
        if (tid == 0) {
            float v = 0.0f;
            #pragma unroll
            for (int w = 0; w < 8; w++) v += warpsum[w];
            const float denom = 1.0f / ((float)NC * (float)HH * (float)WW);
            out[0] = 1.0f - v * denom;
            g_counter = 0;   // self-reset for the next (graph-replayed) call
        }
    }
}

extern "C" void kernel_launch(void* const* d_in, const int* in_sizes, int n_in,
                              void* d_out, int out_size)
{
    (void)in_sizes; (void)n_in; (void)out_size;
    const float* x = (const float*)d_in[0];
    const float* y = (const float*)d_in[1];
    float* out = (float*)d_out;

    dim3 grid(TPX, TPY, NC);
    ssim_structure_kernel<<<grid, NTHREADS>>>(x, y, out);
}